// round 2
// baseline (speedup 1.0000x reference)
#include <cuda_runtime.h>
#include <cstdint>

#define BATCH  8192
#define SEQ    100
#define EMBED  50
#define HID    20
#define NLABEL 15
#define VOCAB  50000

// Precomputed P[v][64] = rearranged(emb_table[v] @ W1 + bi1), padded/owner-major.
// Owner-major layout per row (64 floats): for owner q in 0..3, 16 slots:
//   slots [0..4]  = z-gate cols  q*5 .. q*5+4   (original col  0..19 region)
//   slots [5..9]  = r-gate cols                  (original col 20..39 region)
//   slots [10..14]= h-gate cols                  (original col 40..59 region)
//   slot  [15]    = 0 (pad)
__device__ float g_P[VOCAB * 64];

// ---------------- helpers ----------------

__device__ __forceinline__ unsigned long long fma2(unsigned long long a,
                                                   unsigned long long b,
                                                   unsigned long long c) {
    unsigned long long d;
    asm("fma.rn.f32x2 %0, %1, %2, %3;" : "=l"(d) : "l"(a), "l"(b), "l"(c));
    return d;
}

__device__ __forceinline__ unsigned long long pack2(float f) {
    unsigned long long r;
    unsigned int u = __float_as_uint(f);
    asm("mov.b64 %0, {%1, %1};" : "=l"(r) : "r"(u));
    return r;
}

__device__ __forceinline__ float2 unpack2(unsigned long long v) {
    float2 r;
    asm("mov.b64 {%0, %1}, %2;" : "=f"(r.x), "=f"(r.y) : "l"(v));
    return r;
}

__device__ __forceinline__ float sigf(float x) {
    float e = __expf(-x);
    return __fdividef(1.0f, 1.0f + e);
}

__device__ __forceinline__ float tanh_fast(float x) {
    // accurate enough: exp-based; preactivations are small (weights ~0.05)
    float e = __expf(2.0f * x);
    return (e - 1.0f) * __fdividef(1.0f, e + 1.0f);
}

// rearranged destination index (0..63) -> original gate column (0..59), or -1 for pad
__device__ __forceinline__ int remap_col(int j64) {
    int q = j64 >> 4;
    int jj = j64 & 15;
    if (jj >= 15) return -1;
    int g = jj / 5;
    int l = jj - g * 5;
    return g * HID + q * 5 + l;
}

// ---------------- P precompute kernel ----------------
// P[v][64] = emb[v] @ W1 (rearranged cols) + bi1
#define VPB 64   // vocab rows per block

__global__ void __launch_bounds__(256) prep_P_kernel(const float* __restrict__ emb,
                                                     const float* __restrict__ W1,
                                                     const float* __restrict__ b1) {
    __shared__ __align__(16) float W1r[EMBED][64];   // rearranged W1
    __shared__ float biasr[64];
    __shared__ float embs[VPB][EMBED];

    int tid = threadIdx.x;

    for (int d = tid; d < EMBED * 64; d += 256) {
        int k = d >> 6, j = d & 63;
        int src = remap_col(j);
        W1r[k][j] = (src >= 0) ? W1[k * (3 * HID) + src] : 0.0f;
    }
    if (tid < 64) {
        int src = remap_col(tid);
        biasr[tid] = (src >= 0) ? b1[src] : 0.0f;   // b1[0] row = input bias
    }

    int v0 = blockIdx.x * VPB;
    for (int i = tid; i < VPB * EMBED; i += 256) {
        int vv = i / EMBED, k = i - vv * EMBED;
        int v = v0 + vv;
        embs[vv][k] = (v < VOCAB) ? emb[v * EMBED + k] : 0.0f;
    }
    __syncthreads();

    int d = tid & 63;
    int vbase = tid >> 6;   // 0..3
    #pragma unroll
    for (int i = 0; i < 16; i++) {
        int vl = vbase + 4 * i;
        int v = v0 + vl;
        if (v >= VOCAB) continue;
        float acc = biasr[d];
        #pragma unroll
        for (int k = 0; k < EMBED; k++)
            acc = fmaf(embs[vl][k], W1r[k][d], acc);
        g_P[v * 64 + d] = acc;
    }
}

// ---------------- main fused GRU kernel ----------------
// 4 threads per batch row; thread q owns hidden indices q*5..q*5+4 (all 3 gates).
#define RPB 64   // rows per block (block = 256 threads)

__global__ void __launch_bounds__(256) gru_main_kernel(
    const int*   __restrict__ x,
    const float* __restrict__ U1,
    const float* __restrict__ b1,
    const float* __restrict__ W2,
    const float* __restrict__ U2,
    const float* __restrict__ b2,
    const float* __restrict__ Wd,
    const float* __restrict__ bd,
    float*       __restrict__ out) {

    __shared__ __align__(16) float sU1[HID * 64];
    __shared__ __align__(16) float sW2[HID * 64];
    __shared__ __align__(16) float sU2[HID * 64];
    __shared__ __align__(16) float sbr1[64];
    __shared__ __align__(16) float sbi2[64];
    __shared__ __align__(16) float sbr2[64];
    __shared__ __align__(16) float sWd[HID * 16];
    __shared__ float sbd[16];
    __shared__ __align__(16) float sh1[RPB][HID];
    __shared__ __align__(16) float sh2[RPB][HID];

    int tid = threadIdx.x;

    // stage + rearrange weights (owner-major, 16-slot windows per owner)
    for (int d = tid; d < HID * 64; d += 256) {
        int k = d >> 6, j = d & 63;
        int src = remap_col(j);
        float v1 = 0.0f, v2 = 0.0f, v3 = 0.0f;
        if (src >= 0) {
            int idx = k * (3 * HID) + src;
            v1 = U1[idx]; v2 = W2[idx]; v3 = U2[idx];
        }
        sU1[d] = v1; sW2[d] = v2; sU2[d] = v3;
    }
    if (tid < 64) {
        int src = remap_col(tid);
        float a = 0.0f, bb = 0.0f, c = 0.0f;
        if (src >= 0) {
            a  = b1[3 * HID + src];  // recurrent bias GRU1
            bb = b2[src];            // input bias GRU2
            c  = b2[3 * HID + src];  // recurrent bias GRU2
        }
        sbr1[tid] = a; sbi2[tid] = bb; sbr2[tid] = c;
    }
    for (int d = tid; d < HID * 16; d += 256) {
        int k = d >> 4, j = d & 15;
        sWd[d] = (j < NLABEL) ? Wd[k * NLABEL + j] : 0.0f;
    }
    if (tid < 16) sbd[tid] = (tid < NLABEL) ? bd[tid] : 0.0f;

    int rl = tid >> 2;   // local row 0..63
    int q  = tid & 3;    // owner 0..3
    #pragma unroll
    for (int i = 0; i < 5; i++) { sh1[rl][q * 5 + i] = 0.0f; sh2[rl][q * 5 + i] = 0.0f; }
    __syncthreads();

    int row = blockIdx.x * RPB + rl;
    const int* xr = x + row * SEQ;

    float h1[HID], h2[HID];
    #pragma unroll
    for (int i = 0; i < HID; i++) { h1[i] = 0.0f; h2[i] = 0.0f; }

    const ulonglong2* U1v = reinterpret_cast<const ulonglong2*>(sU1);
    const ulonglong2* W2v = reinterpret_cast<const ulonglong2*>(sW2);
    const ulonglong2* U2v = reinterpret_cast<const ulonglong2*>(sU2);
    const ulonglong2* br1v = reinterpret_cast<const ulonglong2*>(sbr1) + q * 4;
    const ulonglong2* bi2v = reinterpret_cast<const ulonglong2*>(sbi2) + q * 4;
    const ulonglong2* br2v = reinterpret_cast<const ulonglong2*>(sbr2) + q * 4;

    int tok = xr[0];

    for (int t = 0; t < SEQ; t++) {
        // gather precomputed input projection for GRU1 (this thread's 16 slots)
        const float4* pp = reinterpret_cast<const float4*>(g_P + (size_t)tok * 64 + q * 16);
        float px[16];
        {
            float4 p0 = pp[0], p1 = pp[1], p2 = pp[2], p3 = pp[3];
            px[0]=p0.x; px[1]=p0.y; px[2]=p0.z; px[3]=p0.w;
            px[4]=p1.x; px[5]=p1.y; px[6]=p1.z; px[7]=p1.w;
            px[8]=p2.x; px[9]=p2.y; px[10]=p2.z; px[11]=p2.w;
            px[12]=p3.x; px[13]=p3.y; px[14]=p3.z; px[15]=p3.w;
        }
        int ntok = (t < SEQ - 1) ? xr[t + 1] : 0;

        // ---- GRU1: mh = h1 @ U1 + br1 (packed f32x2, 8 accumulators) ----
        unsigned long long acc[8];
        {
            #pragma unroll
            for (int j = 0; j < 4; j++) {
                ulonglong2 tb = br1v[j];
                acc[2 * j] = tb.x; acc[2 * j + 1] = tb.y;
            }
        }
        #pragma unroll
        for (int k = 0; k < HID; k++) {
            unsigned long long hk2 = pack2(h1[k]);
            const ulonglong2* wp = U1v + k * 16 + q * 4;
            #pragma unroll
            for (int j = 0; j < 4; j++) {
                ulonglong2 w = wp[j];
                acc[2 * j]     = fma2(w.x, hk2, acc[2 * j]);
                acc[2 * j + 1] = fma2(w.y, hk2, acc[2 * j + 1]);
            }
        }
        float a[16];
        #pragma unroll
        for (int j = 0; j < 8; j++) {
            float2 f = unpack2(acc[j]);
            a[2 * j] = f.x; a[2 * j + 1] = f.y;
        }

        // GRU1 gate math (z,r,h order; reset_after=True)
        float h1n[5];
        #pragma unroll
        for (int i = 0; i < 5; i++) {
            float z  = sigf(px[i] + a[i]);
            float r  = sigf(px[5 + i] + a[5 + i]);
            float hh = tanh_fast(px[10 + i] + r * a[10 + i]);
            float ho = h1[q * 5 + i];
            h1n[i] = z * ho + (1.0f - z) * hh;
        }
        #pragma unroll
        for (int i = 0; i < 5; i++) sh1[rl][q * 5 + i] = h1n[i];
        __syncwarp();
        #pragma unroll
        for (int i = 0; i < 5; i++) {
            float4 v = reinterpret_cast<const float4*>(sh1[rl])[i];
            h1[4 * i] = v.x; h1[4 * i + 1] = v.y; h1[4 * i + 2] = v.z; h1[4 * i + 3] = v.w;
        }

        // ---- GRU2: mx2 = h1 @ W2 + bi2 ; mh2 = h2 @ U2 + br2 (dual matvec) ----
        unsigned long long ax[8], ah[8];
        #pragma unroll
        for (int j = 0; j < 4; j++) {
            ulonglong2 t1 = bi2v[j]; ax[2 * j] = t1.x; ax[2 * j + 1] = t1.y;
            ulonglong2 t2 = br2v[j]; ah[2 * j] = t2.x; ah[2 * j + 1] = t2.y;
        }
        #pragma unroll
        for (int k = 0; k < HID; k++) {
            unsigned long long a2 = pack2(h1[k]);
            unsigned long long b2p = pack2(h2[k]);
            const ulonglong2* wxp = W2v + k * 16 + q * 4;
            const ulonglong2* whp = U2v + k * 16 + q * 4;
            #pragma unroll
            for (int j = 0; j < 4; j++) {
                ulonglong2 wx = wxp[j];
                ax[2 * j]     = fma2(wx.x, a2, ax[2 * j]);
                ax[2 * j + 1] = fma2(wx.y, a2, ax[2 * j + 1]);
                ulonglong2 wh = whp[j];
                ah[2 * j]     = fma2(wh.x, b2p, ah[2 * j]);
                ah[2 * j + 1] = fma2(wh.y, b2p, ah[2 * j + 1]);
            }
        }
        float bx[16], bh[16];
        #pragma unroll
        for (int j = 0; j < 8; j++) {
            float2 fx = unpack2(ax[j]); bx[2 * j] = fx.x; bx[2 * j + 1] = fx.y;
            float2 fh = unpack2(ah[j]); bh[2 * j] = fh.x; bh[2 * j + 1] = fh.y;
        }

        float h2n[5];
        #pragma unroll
        for (int i = 0; i < 5; i++) {
            float z  = sigf(bx[i] + bh[i]);
            float r  = sigf(bx[5 + i] + bh[5 + i]);
            float hh = tanh_fast(bx[10 + i] + r * bh[10 + i]);
            float ho = h2[q * 5 + i];
            h2n[i] = z * ho + (1.0f - z) * hh;
        }
        #pragma unroll
        for (int i = 0; i < 5; i++) sh2[rl][q * 5 + i] = h2n[i];
        __syncwarp();
        #pragma unroll
        for (int i = 0; i < 5; i++) {
            float4 v = reinterpret_cast<const float4*>(sh2[rl])[i];
            h2[4 * i] = v.x; h2[4 * i + 1] = v.y; h2[4 * i + 2] = v.z; h2[4 * i + 3] = v.w;
        }

        tok = ntok;
    }

    // ---- dense head: logits = h2 @ Wd + bd (thread q -> cols q*4..q*4+3) ----
    #pragma unroll
    for (int c = 0; c < 4; c++) {
        int col = q * 4 + c;
        if (col >= NLABEL) break;
        float accd = sbd[col];
        #pragma unroll
        for (int k = 0; k < HID; k++)
            accd = fmaf(h2[k], sWd[k * 16 + col], accd);
        out[row * NLABEL + col] = accd;
    }
}

// ---------------- launch ----------------
extern "C" void kernel_launch(void* const* d_in, const int* in_sizes, int n_in,
                              void* d_out, int out_size) {
    const int*   x    = (const int*)  d_in[0];
    const float* emb  = (const float*)d_in[1];
    const float* W1   = (const float*)d_in[2];
    const float* U1   = (const float*)d_in[3];
    const float* b1   = (const float*)d_in[4];
    const float* W2   = (const float*)d_in[5];
    const float* U2   = (const float*)d_in[6];
    const float* b2   = (const float*)d_in[7];
    const float* Wd   = (const float*)d_in[8];
    const float* bd   = (const float*)d_in[9];
    float* out = (float*)d_out;

    prep_P_kernel<<<(VOCAB + VPB - 1) / VPB, 256>>>(emb, W1, b1);
    gru_main_kernel<<<BATCH / RPB, 256>>>(x, U1, b1, W2, U2, b2, Wd, bd, out);
}

// round 6
// speedup vs baseline: 1.9163x; 1.9163x over previous
#include <cuda_runtime.h>
#include <cstdint>

#define BATCH  8192
#define SEQ    100
#define EMBED  50
#define HID    20
#define NLABEL 15
#define VOCAB  50000

// Precomputed P[v][64] = rearranged(emb_table[v] @ W1 + bi1), owner-major:
// owner q (0..3) gets 16 slots: [0..4]=z cols q*5.., [5..9]=r, [10..14]=h, [15]=pad
__device__ float g_P[VOCAB * 64];

// ---------------- helpers ----------------
__device__ __forceinline__ unsigned long long fma2(unsigned long long a,
                                                   unsigned long long b,
                                                   unsigned long long c) {
    unsigned long long d;
    asm("fma.rn.f32x2 %0, %1, %2, %3;" : "=l"(d) : "l"(a), "l"(b), "l"(c));
    return d;
}
__device__ __forceinline__ unsigned long long pack2(float f) {
    unsigned long long r;
    unsigned int u = __float_as_uint(f);
    asm("mov.b64 %0, {%1, %1};" : "=l"(r) : "r"(u));
    return r;
}
__device__ __forceinline__ float2 unpack2(unsigned long long v) {
    float2 r;
    asm("mov.b64 {%0, %1}, %2;" : "=f"(r.x), "=f"(r.y) : "l"(v));
    return r;
}
__device__ __forceinline__ float tanha(float x) {
    float y;
    asm("tanh.approx.f32 %0, %1;" : "=f"(y) : "f"(x));
    return y;
}
// rearranged slot index (0..63) -> original gate column (0..59), or -1 pad
__device__ __forceinline__ int remap_col(int j64) {
    int q = j64 >> 4;
    int jj = j64 & 15;
    if (jj >= 15) return -1;
    int g = jj / 5;
    int l = jj - g * 5;
    return g * HID + q * 5 + l;
}

// ---------------- P precompute ----------------
#define VPB 64
__global__ void __launch_bounds__(256) prep_P_kernel(const float* __restrict__ emb,
                                                     const float* __restrict__ W1,
                                                     const float* __restrict__ b1) {
    __shared__ __align__(16) float W1r[EMBED][64];
    __shared__ float biasr[64];
    __shared__ float embs[VPB][EMBED];
    int tid = threadIdx.x;
    for (int d = tid; d < EMBED * 64; d += 256) {
        int k = d >> 6, j = d & 63;
        int src = remap_col(j);
        W1r[k][j] = (src >= 0) ? W1[k * (3 * HID) + src] : 0.0f;
    }
    if (tid < 64) {
        int src = remap_col(tid);
        biasr[tid] = (src >= 0) ? b1[src] : 0.0f;
    }
    int v0 = blockIdx.x * VPB;
    for (int i = tid; i < VPB * EMBED; i += 256) {
        int vv = i / EMBED, k = i - vv * EMBED;
        int v = v0 + vv;
        embs[vv][k] = (v < VOCAB) ? emb[v * EMBED + k] : 0.0f;
    }
    __syncthreads();
    int d = tid & 63;
    int vbase = tid >> 6;
    #pragma unroll
    for (int i = 0; i < 16; i++) {
        int vl = vbase + 4 * i;
        int v = v0 + vl;
        if (v >= VOCAB) continue;
        float acc = biasr[d];
        #pragma unroll
        for (int k = 0; k < EMBED; k++)
            acc = fmaf(embs[vl][k], W1r[k][d], acc);
        g_P[v * 64 + d] = acc;
    }
}

// ---------------- main fused GRU kernel ----------------
// 4 threads per row; thread q owns hidden indices q*5..q*5+4 (all 3 gates).
// Pipelined: iteration t computes GRU2(t) and GRU1(t+1) together (both only
// need h1(t), h2(t)) -> one merged k-loop, 24 independent f32x2 chains.
#define RPB    56
#define BLOCK  (RPB * 4)

// interleaved weights: [k][mat][j][q][4]  (mat: 0=U1,1=W2,2=U2)
__global__ void __launch_bounds__(BLOCK) gru_main_kernel(
    const int*   __restrict__ x,
    const float* __restrict__ U1,
    const float* __restrict__ b1,
    const float* __restrict__ W2,
    const float* __restrict__ U2,
    const float* __restrict__ b2,
    const float* __restrict__ Wd,
    const float* __restrict__ bd,
    float*       __restrict__ out) {

    __shared__ __align__(16) float sW[HID * 3 * 64];   // 15360 B
    __shared__ __align__(16) float sbr1[64];
    __shared__ __align__(16) float sbi2[64];
    __shared__ __align__(16) float sbr2[64];
    __shared__ __align__(16) float sWd[HID * 16];
    __shared__ float sbd[16];
    __shared__ __align__(16) float sh1[RPB][HID];
    __shared__ __align__(16) float sh2[RPB][HID];

    int tid = threadIdx.x;

    // stage interleaved weights
    for (int d = tid; d < HID * 3 * 64; d += BLOCK) {
        int k   = d / 192;
        int rem = d - k * 192;
        int mat = rem >> 6;
        int s64 = rem & 63;            // (j*4+q)*4+c
        int j   = s64 >> 4;
        int q_  = (s64 >> 2) & 3;
        int c   = s64 & 3;
        int jj  = j * 4 + c;           // slot within owner
        int src = remap_col(q_ * 16 + jj);
        float v = 0.0f;
        if (src >= 0) {
            int idx = k * (3 * HID) + src;
            v = (mat == 0) ? U1[idx] : (mat == 1) ? W2[idx] : U2[idx];
        }
        sW[d] = v;
    }
    if (tid < 64) {
        int src = remap_col(tid);
        float a = 0.0f, bb = 0.0f, c = 0.0f;
        if (src >= 0) {
            a  = b1[3 * HID + src];
            bb = b2[src];
            c  = b2[3 * HID + src];
        }
        sbr1[tid] = a; sbi2[tid] = bb; sbr2[tid] = c;
    }
    for (int d = tid; d < HID * 16; d += BLOCK) {
        int k = d >> 4, j = d & 15;
        sWd[d] = (j < NLABEL) ? Wd[k * NLABEL + j] : 0.0f;
    }
    if (tid < 16) sbd[tid] = (tid < NLABEL) ? bd[tid] : 0.0f;
    __syncthreads();

    int rl  = tid >> 2;
    int q   = tid & 3;
    int row = blockIdx.x * RPB + rl;
    if (row >= BATCH) return;          // whole warps idle in last block only

    const int* xr = x + row * SEQ;

    float h1[HID], h2[HID];
    #pragma unroll
    for (int i = 0; i < HID; i++) { h1[i] = 0.0f; h2[i] = 0.0f; }

    const ulonglong2* br1v = reinterpret_cast<const ulonglong2*>(sbr1) + q * 4;
    const ulonglong2* bi2v = reinterpret_cast<const ulonglong2*>(sbi2) + q * 4;
    const ulonglong2* br2v = reinterpret_cast<const ulonglong2*>(sbr2) + q * 4;

    // -------- prologue: GRU1(0) (h1 = 0 -> mh = br1) --------
    int tok = xr[0];
    {
        const float4* pp = reinterpret_cast<const float4*>(g_P + (size_t)tok * 64 + q * 16);
        float4 p0 = pp[0], p1 = pp[1], p2 = pp[2];
        float pz[5] = {p0.x, p0.y, p0.z, p0.w, p1.x};
        float pr[5] = {p1.y, p1.z, p1.w, p2.x, p2.y};
        float ph[5] = {p2.z, p2.w, 0.f, 0.f, 0.f};
        {   // remaining h-gate slots 12..14
            const float* pf = g_P + (size_t)tok * 64 + q * 16;
            ph[2] = pf[12]; ph[3] = pf[13]; ph[4] = pf[14];
        }
        #pragma unroll
        for (int i = 0; i < 5; i++) {
            float a0 = sbr1[q * 16 + i];
            float a1 = sbr1[q * 16 + 5 + i];
            float a2 = sbr1[q * 16 + 10 + i];
            float zt = tanha(0.5f * (pz[i] + a0));
            float r  = 0.5f + 0.5f * tanha(0.5f * (pr[i] + a1));
            float hh = tanha(ph[i] + r * a2);
            sh1[rl][q * 5 + i] = 0.5f * hh - 0.5f * zt * hh;   // ho = 0
        }
        __syncwarp();
        #pragma unroll
        for (int i = 0; i < 5; i++) {
            float4 v = reinterpret_cast<const float4*>(sh1[rl])[i];
            h1[4*i] = v.x; h1[4*i+1] = v.y; h1[4*i+2] = v.z; h1[4*i+3] = v.w;
        }
        __syncwarp();
    }

    int tok_next = xr[1];

    // -------- main loop: iteration t does GRU2(t) and GRU1(t+1) --------
    for (int t = 0; t < SEQ - 1; t++) {
        // prefetch input projection for GRU1(t+1) (consumed after k-loop)
        const float4* pp = reinterpret_cast<const float4*>(g_P + (size_t)tok_next * 64 + q * 16);
        float4 p0 = pp[0], p1 = pp[1], p2 = pp[2], p3 = pp[3];
        int t2 = t + 2;
        tok_next = xr[(t2 < SEQ) ? t2 : (SEQ - 1)];

        unsigned long long A[8], X[8], H[8];   // U1-acc, W2-acc, U2-acc
        #pragma unroll
        for (int j = 0; j < 4; j++) {
            ulonglong2 ta = br1v[j]; A[2*j] = ta.x; A[2*j+1] = ta.y;
            ulonglong2 tx = bi2v[j]; X[2*j] = tx.x; X[2*j+1] = tx.y;
            ulonglong2 th = br2v[j]; H[2*j] = th.x; H[2*j+1] = th.y;
        }
        #pragma unroll
        for (int k = 0; k < HID; k++) {
            unsigned long long h1p = pack2(h1[k]);
            unsigned long long h2p = pack2(h2[k]);
            const ulonglong2* wk = reinterpret_cast<const ulonglong2*>(sW + k * 192);
            #pragma unroll
            for (int j = 0; j < 4; j++) {
                ulonglong2 w0 = wk[0 * 16 + j * 4 + q];   // U1
                A[2*j]   = fma2(w0.x, h1p, A[2*j]);
                A[2*j+1] = fma2(w0.y, h1p, A[2*j+1]);
                ulonglong2 w1 = wk[1 * 16 + j * 4 + q];   // W2
                X[2*j]   = fma2(w1.x, h1p, X[2*j]);
                X[2*j+1] = fma2(w1.y, h1p, X[2*j+1]);
                ulonglong2 w2 = wk[2 * 16 + j * 4 + q];   // U2
                H[2*j]   = fma2(w2.x, h2p, H[2*j]);
                H[2*j+1] = fma2(w2.y, h2p, H[2*j+1]);
            }
        }

        float a[16], bx[16], bh[16];
        #pragma unroll
        for (int j = 0; j < 8; j++) {
            float2 fa = unpack2(A[j]); a[2*j]  = fa.x; a[2*j+1]  = fa.y;
            float2 fx = unpack2(X[j]); bx[2*j] = fx.x; bx[2*j+1] = fx.y;
            float2 fh = unpack2(H[j]); bh[2*j] = fh.x; bh[2*j+1] = fh.y;
        }
        float px[16] = {p0.x,p0.y,p0.z,p0.w, p1.x,p1.y,p1.z,p1.w,
                        p2.x,p2.y,p2.z,p2.w, p3.x,p3.y,p3.z,p3.w};

        // GRU2(t) gates
        #pragma unroll
        for (int i = 0; i < 5; i++) {
            float zt = tanha(0.5f * (bx[i] + bh[i]));
            float r  = 0.5f + 0.5f * tanha(0.5f * (bx[5+i] + bh[5+i]));
            float hh = tanha(bx[10+i] + r * bh[10+i]);
            float ho = h2[q * 5 + i];
            sh2[rl][q * 5 + i] = 0.5f * (ho + hh) + 0.5f * zt * (ho - hh);
        }
        // GRU1(t+1) gates
        #pragma unroll
        for (int i = 0; i < 5; i++) {
            float zt = tanha(0.5f * (px[i] + a[i]));
            float r  = 0.5f + 0.5f * tanha(0.5f * (px[5+i] + a[5+i]));
            float hh = tanha(px[10+i] + r * a[10+i]);
            float ho = h1[q * 5 + i];
            sh1[rl][q * 5 + i] = 0.5f * (ho + hh) + 0.5f * zt * (ho - hh);
        }
        __syncwarp();
        #pragma unroll
        for (int i = 0; i < 5; i++) {
            float4 v1 = reinterpret_cast<const float4*>(sh1[rl])[i];
            h1[4*i] = v1.x; h1[4*i+1] = v1.y; h1[4*i+2] = v1.z; h1[4*i+3] = v1.w;
            float4 v2 = reinterpret_cast<const float4*>(sh2[rl])[i];
            h2[4*i] = v2.x; h2[4*i+1] = v2.y; h2[4*i+2] = v2.z; h2[4*i+3] = v2.w;
        }
        __syncwarp();
    }

    // -------- epilogue: GRU2(SEQ-1) --------
    {
        unsigned long long X[8], H[8];
        #pragma unroll
        for (int j = 0; j < 4; j++) {
            ulonglong2 tx = bi2v[j]; X[2*j] = tx.x; X[2*j+1] = tx.y;
            ulonglong2 th = br2v[j]; H[2*j] = th.x; H[2*j+1] = th.y;
        }
        #pragma unroll
        for (int k = 0; k < HID; k++) {
            unsigned long long h1p = pack2(h1[k]);
            unsigned long long h2p = pack2(h2[k]);
            const ulonglong2* wk = reinterpret_cast<const ulonglong2*>(sW + k * 192);
            #pragma unroll
            for (int j = 0; j < 4; j++) {
                ulonglong2 w1 = wk[1 * 16 + j * 4 + q];
                X[2*j]   = fma2(w1.x, h1p, X[2*j]);
                X[2*j+1] = fma2(w1.y, h1p, X[2*j+1]);
                ulonglong2 w2 = wk[2 * 16 + j * 4 + q];
                H[2*j]   = fma2(w2.x, h2p, H[2*j]);
                H[2*j+1] = fma2(w2.y, h2p, H[2*j+1]);
            }
        }
        float bx[16], bh[16];
        #pragma unroll
        for (int j = 0; j < 8; j++) {
            float2 fx = unpack2(X[j]); bx[2*j] = fx.x; bx[2*j+1] = fx.y;
            float2 fh = unpack2(H[j]); bh[2*j] = fh.x; bh[2*j+1] = fh.y;
        }
        #pragma unroll
        for (int i = 0; i < 5; i++) {
            float zt = tanha(0.5f * (bx[i] + bh[i]));
            float r  = 0.5f + 0.5f * tanha(0.5f * (bx[5+i] + bh[5+i]));
            float hh = tanha(bx[10+i] + r * bh[10+i]);
            float ho = h2[q * 5 + i];
            sh2[rl][q * 5 + i] = 0.5f * (ho + hh) + 0.5f * zt * (ho - hh);
        }
        __syncwarp();
        #pragma unroll
        for (int i = 0; i < 5; i++) {
            float4 v2 = reinterpret_cast<const float4*>(sh2[rl])[i];
            h2[4*i] = v2.x; h2[4*i+1] = v2.y; h2[4*i+2] = v2.z; h2[4*i+3] = v2.w;
        }
    }

    // -------- dense head --------
    #pragma unroll
    for (int c = 0; c < 4; c++) {
        int col = q * 4 + c;
        if (col >= NLABEL) break;
        float accd = sbd[col];
        #pragma unroll
        for (int k = 0; k < HID; k++)
            accd = fmaf(h2[k], sWd[k * 16 + col], accd);
        out[row * NLABEL + col] = accd;
    }
}

// ---------------- launch ----------------
extern "C" void kernel_launch(void* const* d_in, const int* in_sizes, int n_in,
                              void* d_out, int out_size) {
    const int*   x    = (const int*)  d_in[0];
    const float* emb  = (const float*)d_in[1];
    const float* W1   = (const float*)d_in[2];
    const float* U1   = (const float*)d_in[3];
    const float* b1   = (const float*)d_in[4];
    const float* W2   = (const float*)d_in[5];
    const float* U2   = (const float*)d_in[6];
    const float* b2   = (const float*)d_in[7];
    const float* Wd   = (const float*)d_in[8];
    const float* bd   = (const float*)d_in[9];
    float* out = (float*)d_out;

    prep_P_kernel<<<(VOCAB + VPB - 1) / VPB, 256>>>(emb, W1, b1);
    gru_main_kernel<<<(BATCH + RPB - 1) / RPB, BLOCK>>>(x, U1, b1, W2, U2, b2, Wd, bd, out);
}

// round 7
// speedup vs baseline: 2.6075x; 1.3607x over previous
#include <cuda_runtime.h>
#include <cstdint>

#define BATCH  8192
#define SEQ    100
#define EMBED  50
#define HID    20
#define NLABEL 15
#define VOCAB  50000

// Precomputed P[v][64] = rearranged(emb_table[v] @ W1 + bi1), owner-major:
// owner q (0..3) gets 16 slots: [0..4]=z cols q*5.., [5..9]=r, [10..14]=h, [15]=pad
__device__ float g_P[VOCAB * 64];

// ---------------- helpers ----------------
__device__ __forceinline__ unsigned long long fma2(unsigned long long a,
                                                   unsigned long long b,
                                                   unsigned long long c) {
    unsigned long long d;
    asm("fma.rn.f32x2 %0, %1, %2, %3;" : "=l"(d) : "l"(a), "l"(b), "l"(c));
    return d;
}
__device__ __forceinline__ unsigned long long pack2(float f) {
    unsigned long long r;
    unsigned int u = __float_as_uint(f);
    asm("mov.b64 %0, {%1, %1};" : "=l"(r) : "r"(u));
    return r;
}
__device__ __forceinline__ float2 unpack2(unsigned long long v) {
    float2 r;
    asm("mov.b64 {%0, %1}, %2;" : "=f"(r.x), "=f"(r.y) : "l"(v));
    return r;
}
__device__ __forceinline__ float tanha(float x) {
    float y;
    asm("tanh.approx.f32 %0, %1;" : "=f"(y) : "f"(x));
    return y;
}
// rearranged slot index (0..63) -> original gate column (0..59), or -1 pad
__device__ __forceinline__ int remap_col(int j64) {
    int q = j64 >> 4;
    int jj = j64 & 15;
    if (jj >= 15) return -1;
    int g = jj / 5;
    int l = jj - g * 5;
    return g * HID + q * 5 + l;
}

// ---------------- P precompute ----------------
#define VPB 64
__global__ void __launch_bounds__(256) prep_P_kernel(const float* __restrict__ emb,
                                                     const float* __restrict__ W1,
                                                     const float* __restrict__ b1) {
    __shared__ __align__(16) float W1r[EMBED][64];
    __shared__ float biasr[64];
    __shared__ float embs[VPB][EMBED];
    int tid = threadIdx.x;
    for (int d = tid; d < EMBED * 64; d += 256) {
        int k = d >> 6, j = d & 63;
        int src = remap_col(j);
        W1r[k][j] = (src >= 0) ? W1[k * (3 * HID) + src] : 0.0f;
    }
    if (tid < 64) {
        int src = remap_col(tid);
        biasr[tid] = (src >= 0) ? b1[src] : 0.0f;
    }
    int v0 = blockIdx.x * VPB;
    for (int i = tid; i < VPB * EMBED; i += 256) {
        int vv = i / EMBED, k = i - vv * EMBED;
        int v = v0 + vv;
        embs[vv][k] = (v < VOCAB) ? emb[v * EMBED + k] : 0.0f;
    }
    __syncthreads();
    int d = tid & 63;
    int vbase = tid >> 6;
    #pragma unroll
    for (int i = 0; i < 16; i++) {
        int vl = vbase + 4 * i;
        int v = v0 + vl;
        if (v >= VOCAB) continue;
        float acc = biasr[d];
        #pragma unroll
        for (int k = 0; k < EMBED; k++)
            acc = fmaf(embs[vl][k], W1r[k][d], acc);
        g_P[v * 64 + d] = acc;
    }
}

// ---------------- main fused GRU kernel ----------------
// 4 threads (owners q=0..3) x 2 rows per thread. Thread q owns hidden
// indices q*5..q*5+4 (all 3 gates) of BOTH its rows, reusing every weight
// load for two rows. h-state lives in shared (stride-21 rows, conflict-free);
// per-step exchange is group-local (__syncwarp with 4-lane masks).
#define RPB     56
#define PPB     28          // row-pairs per block
#define BLOCK   128
#define HSTRIDE 21

__global__ void __launch_bounds__(BLOCK) gru_main_kernel(
    const int*   __restrict__ x,
    const float* __restrict__ U1,
    const float* __restrict__ b1,
    const float* __restrict__ W2,
    const float* __restrict__ U2,
    const float* __restrict__ b2,
    const float* __restrict__ Wd,
    const float* __restrict__ bd,
    float*       __restrict__ out) {

    __shared__ __align__(16) float sW[HID * 192];   // [k][mat][j][q][4]
    __shared__ __align__(16) float sbr1[64];
    __shared__ __align__(16) float sbi2[64];
    __shared__ __align__(16) float sbr2[64];
    __shared__ __align__(16) float sWd[HID * 16];
    __shared__ float sbd[16];
    __shared__ __align__(16) float sh1[64 * HSTRIDE];
    __shared__ __align__(16) float sh2[64 * HSTRIDE];

    int tid = threadIdx.x;

    // ---- stage interleaved weights ----
    for (int d = tid; d < HID * 192; d += BLOCK) {
        int k   = d / 192;
        int rem = d - k * 192;
        int mat = rem >> 6;
        int s64 = rem & 63;            // (j*4+q)*4+c
        int j   = s64 >> 4;
        int q_  = (s64 >> 2) & 3;
        int c   = s64 & 3;
        int jj  = j * 4 + c;
        int src = remap_col(q_ * 16 + jj);
        float v = 0.0f;
        if (src >= 0) {
            int idx = k * (3 * HID) + src;
            v = (mat == 0) ? U1[idx] : (mat == 1) ? W2[idx] : U2[idx];
        }
        sW[d] = v;
    }
    if (tid < 64) {
        int src = remap_col(tid);
        float a = 0.0f, bb = 0.0f, c = 0.0f;
        if (src >= 0) {
            a  = b1[3 * HID + src];
            bb = b2[src];
            c  = b2[3 * HID + src];
        }
        sbr1[tid] = a; sbi2[tid] = bb; sbr2[tid] = c;
    }
    for (int d = tid; d < HID * 16; d += BLOCK) {
        int k = d >> 4, j = d & 15;
        sWd[d] = (j < NLABEL) ? Wd[k * NLABEL + j] : 0.0f;
    }
    if (tid < 16) sbd[tid] = (tid < NLABEL) ? bd[tid] : 0.0f;
    __syncthreads();

    int rp = tid >> 2;      // row-pair 0..31 (>=28 idle)
    int q  = tid & 3;
    int rowa = blockIdx.x * RPB + rp * 2;
    if (rp >= PPB || rowa >= BATCH) return;

    int lane = tid & 31;
    unsigned gmask = 0xFu << (lane & ~3);

    int rla = rp * 2, rlb = rla + 1;
    float* ph1a = sh1 + rla * HSTRIDE;
    float* ph1b = sh1 + rlb * HSTRIDE;
    float* ph2a = sh2 + rla * HSTRIDE;
    float* ph2b = sh2 + rlb * HSTRIDE;

    const int* xa = x + (size_t)rowa * SEQ;
    const int* xb = xa + SEQ;

    const ulonglong2* br1v = reinterpret_cast<const ulonglong2*>(sbr1) + q * 4;
    const ulonglong2* bi2v = reinterpret_cast<const ulonglong2*>(sbi2) + q * 4;
    const ulonglong2* br2v = reinterpret_cast<const ulonglong2*>(sbr2) + q * 4;

    float h1oa[5], h1ob[5], h2oa[5], h2ob[5];
    #pragma unroll
    for (int i = 0; i < 5; i++) {
        h1oa[i] = 0.f; h1ob[i] = 0.f; h2oa[i] = 0.f; h2ob[i] = 0.f;
        ph2a[q * 5 + i] = 0.f;        // GRU2 state starts at 0
        ph2b[q * 5 + i] = 0.f;
    }

    // -------- prologue: GRU1(0) for both rows (h1 = 0 -> mh = br1) --------
    int toka = xa[0], tokb = xb[0];
    {
        const float4* ppa = reinterpret_cast<const float4*>(g_P + (size_t)toka * 64 + q * 16);
        const float4* ppb = reinterpret_cast<const float4*>(g_P + (size_t)tokb * 64 + q * 16);
        float4 a0 = ppa[0], a1 = ppa[1], a2 = ppa[2], a3 = ppa[3];
        float4 b0 = ppb[0], b1_ = ppb[1], b2_ = ppb[2], b3 = ppb[3];
        float pxa[16] = {a0.x,a0.y,a0.z,a0.w, a1.x,a1.y,a1.z,a1.w,
                         a2.x,a2.y,a2.z,a2.w, a3.x,a3.y,a3.z,a3.w};
        float pxb[16] = {b0.x,b0.y,b0.z,b0.w, b1_.x,b1_.y,b1_.z,b1_.w,
                         b2_.x,b2_.y,b2_.z,b2_.w, b3.x,b3.y,b3.z,b3.w};
        #pragma unroll
        for (int i = 0; i < 5; i++) {
            float c0 = sbr1[q * 16 + i];
            float c1 = sbr1[q * 16 + 5 + i];
            float c2 = sbr1[q * 16 + 10 + i];
            {
                float zt = tanha(0.5f * (pxa[i] + c0));
                float r  = 0.5f + 0.5f * tanha(0.5f * (pxa[5 + i] + c1));
                float hh = tanha(pxa[10 + i] + r * c2);
                h1oa[i] = 0.5f * hh - 0.5f * zt * hh;
            }
            {
                float zt = tanha(0.5f * (pxb[i] + c0));
                float r  = 0.5f + 0.5f * tanha(0.5f * (pxb[5 + i] + c1));
                float hh = tanha(pxb[10 + i] + r * c2);
                h1ob[i] = 0.5f * hh - 0.5f * zt * hh;
            }
            ph1a[q * 5 + i] = h1oa[i];
            ph1b[q * 5 + i] = h1ob[i];
        }
        __syncwarp(gmask);
    }

    int tok_na = xa[1], tok_nb = xb[1];

    // -------- main loop: iteration t does GRU2(t) and GRU1(t+1) --------
    for (int t = 0; t < SEQ - 1; t++) {
        unsigned long long Aa[8], Ab[8], Xa[8], Xb[8], Ha[8], Hb[8];
        #pragma unroll
        for (int j = 0; j < 4; j++) {
            ulonglong2 ta = br1v[j]; Aa[2*j] = ta.x; Aa[2*j+1] = ta.y;
                                     Ab[2*j] = ta.x; Ab[2*j+1] = ta.y;
            ulonglong2 tx = bi2v[j]; Xa[2*j] = tx.x; Xa[2*j+1] = tx.y;
                                     Xb[2*j] = tx.x; Xb[2*j+1] = tx.y;
            ulonglong2 th = br2v[j]; Ha[2*j] = th.x; Ha[2*j+1] = th.y;
                                     Hb[2*j] = th.x; Hb[2*j+1] = th.y;
        }
        #pragma unroll 5
        for (int k = 0; k < HID; k++) {
            unsigned long long h1ap = pack2(ph1a[k]);
            unsigned long long h1bp = pack2(ph1b[k]);
            unsigned long long h2ap = pack2(ph2a[k]);
            unsigned long long h2bp = pack2(ph2b[k]);
            const ulonglong2* wk = reinterpret_cast<const ulonglong2*>(sW + k * 192);
            #pragma unroll
            for (int j = 0; j < 4; j++) {
                ulonglong2 w0 = wk[0 * 16 + j * 4 + q];   // U1
                Aa[2*j]   = fma2(w0.x, h1ap, Aa[2*j]);
                Aa[2*j+1] = fma2(w0.y, h1ap, Aa[2*j+1]);
                Ab[2*j]   = fma2(w0.x, h1bp, Ab[2*j]);
                Ab[2*j+1] = fma2(w0.y, h1bp, Ab[2*j+1]);
                ulonglong2 w1 = wk[1 * 16 + j * 4 + q];   // W2
                Xa[2*j]   = fma2(w1.x, h1ap, Xa[2*j]);
                Xa[2*j+1] = fma2(w1.y, h1ap, Xa[2*j+1]);
                Xb[2*j]   = fma2(w1.x, h1bp, Xb[2*j]);
                Xb[2*j+1] = fma2(w1.y, h1bp, Xb[2*j+1]);
                ulonglong2 w2 = wk[2 * 16 + j * 4 + q];   // U2
                Ha[2*j]   = fma2(w2.x, h2ap, Ha[2*j]);
                Ha[2*j+1] = fma2(w2.y, h2ap, Ha[2*j+1]);
                Hb[2*j]   = fma2(w2.x, h2bp, Hb[2*j]);
                Hb[2*j+1] = fma2(w2.y, h2bp, Hb[2*j+1]);
            }
        }

        // input projections for GRU1(t+1)
        const float4* ppa = reinterpret_cast<const float4*>(g_P + (size_t)tok_na * 64 + q * 16);
        const float4* ppb = reinterpret_cast<const float4*>(g_P + (size_t)tok_nb * 64 + q * 16);
        float4 pa0 = ppa[0], pa1 = ppa[1], pa2 = ppa[2], pa3 = ppa[3];
        float4 pb0 = ppb[0], pb1 = ppb[1], pb2 = ppb[2], pb3 = ppb[3];
        int t2 = t + 2;
        int idx2 = (t2 < SEQ) ? t2 : (SEQ - 1);
        tok_na = xa[idx2];
        tok_nb = xb[idx2];

        // ---- row a gates ----
        {
            float a[16], bx[16], bh[16];
            #pragma unroll
            for (int j = 0; j < 8; j++) {
                float2 fa = unpack2(Aa[j]); a[2*j]  = fa.x; a[2*j+1]  = fa.y;
                float2 fx = unpack2(Xa[j]); bx[2*j] = fx.x; bx[2*j+1] = fx.y;
                float2 fh = unpack2(Ha[j]); bh[2*j] = fh.x; bh[2*j+1] = fh.y;
            }
            float px[16] = {pa0.x,pa0.y,pa0.z,pa0.w, pa1.x,pa1.y,pa1.z,pa1.w,
                            pa2.x,pa2.y,pa2.z,pa2.w, pa3.x,pa3.y,pa3.z,pa3.w};
            #pragma unroll
            for (int i = 0; i < 5; i++) {
                float zt = tanha(0.5f * (bx[i] + bh[i]));
                float r  = 0.5f + 0.5f * tanha(0.5f * (bx[5+i] + bh[5+i]));
                float hh = tanha(bx[10+i] + r * bh[10+i]);
                float ho = h2oa[i];
                h2oa[i] = 0.5f * (ho + hh) + 0.5f * zt * (ho - hh);
            }
            #pragma unroll
            for (int i = 0; i < 5; i++) {
                float zt = tanha(0.5f * (px[i] + a[i]));
                float r  = 0.5f + 0.5f * tanha(0.5f * (px[5+i] + a[5+i]));
                float hh = tanha(px[10+i] + r * a[10+i]);
                float ho = h1oa[i];
                h1oa[i] = 0.5f * (ho + hh) + 0.5f * zt * (ho - hh);
            }
        }
        // ---- row b gates ----
        {
            float a[16], bx[16], bh[16];
            #pragma unroll
            for (int j = 0; j < 8; j++) {
                float2 fa = unpack2(Ab[j]); a[2*j]  = fa.x; a[2*j+1]  = fa.y;
                float2 fx = unpack2(Xb[j]); bx[2*j] = fx.x; bx[2*j+1] = fx.y;
                float2 fh = unpack2(Hb[j]); bh[2*j] = fh.x; bh[2*j+1] = fh.y;
            }
            float px[16] = {pb0.x,pb0.y,pb0.z,pb0.w, pb1.x,pb1.y,pb1.z,pb1.w,
                            pb2.x,pb2.y,pb2.z,pb2.w, pb3.x,pb3.y,pb3.z,pb3.w};
            #pragma unroll
            for (int i = 0; i < 5; i++) {
                float zt = tanha(0.5f * (bx[i] + bh[i]));
                float r  = 0.5f + 0.5f * tanha(0.5f * (bx[5+i] + bh[5+i]));
                float hh = tanha(bx[10+i] + r * bh[10+i]);
                float ho = h2ob[i];
                h2ob[i] = 0.5f * (ho + hh) + 0.5f * zt * (ho - hh);
            }
            #pragma unroll
            for (int i = 0; i < 5; i++) {
                float zt = tanha(0.5f * (px[i] + a[i]));
                float r  = 0.5f + 0.5f * tanha(0.5f * (px[5+i] + a[5+i]));
                float hh = tanha(px[10+i] + r * a[10+i]);
                float ho = h1ob[i];
                h1ob[i] = 0.5f * (ho + hh) + 0.5f * zt * (ho - hh);
            }
        }

        __syncwarp(gmask);   // all group reads of old h done
        #pragma unroll
        for (int i = 0; i < 5; i++) {
            ph1a[q * 5 + i] = h1oa[i];
            ph1b[q * 5 + i] = h1ob[i];
            ph2a[q * 5 + i] = h2oa[i];
            ph2b[q * 5 + i] = h2ob[i];
        }
        __syncwarp(gmask);   // new h visible to group
    }

    // -------- epilogue: GRU2(SEQ-1) --------
    {
        unsigned long long Xa[8], Xb[8], Ha[8], Hb[8];
        #pragma unroll
        for (int j = 0; j < 4; j++) {
            ulonglong2 tx = bi2v[j]; Xa[2*j] = tx.x; Xa[2*j+1] = tx.y;
                                     Xb[2*j] = tx.x; Xb[2*j+1] = tx.y;
            ulonglong2 th = br2v[j]; Ha[2*j] = th.x; Ha[2*j+1] = th.y;
                                     Hb[2*j] = th.x; Hb[2*j+1] = th.y;
        }
        #pragma unroll 5
        for (int k = 0; k < HID; k++) {
            unsigned long long h1ap = pack2(ph1a[k]);
            unsigned long long h1bp = pack2(ph1b[k]);
            unsigned long long h2ap = pack2(ph2a[k]);
            unsigned long long h2bp = pack2(ph2b[k]);
            const ulonglong2* wk = reinterpret_cast<const ulonglong2*>(sW + k * 192);
            #pragma unroll
            for (int j = 0; j < 4; j++) {
                ulonglong2 w1 = wk[1 * 16 + j * 4 + q];
                Xa[2*j]   = fma2(w1.x, h1ap, Xa[2*j]);
                Xa[2*j+1] = fma2(w1.y, h1ap, Xa[2*j+1]);
                Xb[2*j]   = fma2(w1.x, h1bp, Xb[2*j]);
                Xb[2*j+1] = fma2(w1.y, h1bp, Xb[2*j+1]);
                ulonglong2 w2 = wk[2 * 16 + j * 4 + q];
                Ha[2*j]   = fma2(w2.x, h2ap, Ha[2*j]);
                Ha[2*j+1] = fma2(w2.y, h2ap, Ha[2*j+1]);
                Hb[2*j]   = fma2(w2.x, h2bp, Hb[2*j]);
                Hb[2*j+1] = fma2(w2.y, h2bp, Hb[2*j+1]);
            }
        }
        {
            float bx[16], bh[16];
            #pragma unroll
            for (int j = 0; j < 8; j++) {
                float2 fx = unpack2(Xa[j]); bx[2*j] = fx.x; bx[2*j+1] = fx.y;
                float2 fh = unpack2(Ha[j]); bh[2*j] = fh.x; bh[2*j+1] = fh.y;
            }
            #pragma unroll
            for (int i = 0; i < 5; i++) {
                float zt = tanha(0.5f * (bx[i] + bh[i]));
                float r  = 0.5f + 0.5f * tanha(0.5f * (bx[5+i] + bh[5+i]));
                float hh = tanha(bx[10+i] + r * bh[10+i]);
                float ho = h2oa[i];
                h2oa[i] = 0.5f * (ho + hh) + 0.5f * zt * (ho - hh);
            }
        }
        {
            float bx[16], bh[16];
            #pragma unroll
            for (int j = 0; j < 8; j++) {
                float2 fx = unpack2(Xb[j]); bx[2*j] = fx.x; bx[2*j+1] = fx.y;
                float2 fh = unpack2(Hb[j]); bh[2*j] = fh.x; bh[2*j+1] = fh.y;
            }
            #pragma unroll
            for (int i = 0; i < 5; i++) {
                float zt = tanha(0.5f * (bx[i] + bh[i]));
                float r  = 0.5f + 0.5f * tanha(0.5f * (bx[5+i] + bh[5+i]));
                float hh = tanha(bx[10+i] + r * bh[10+i]);
                float ho = h2ob[i];
                h2ob[i] = 0.5f * (ho + hh) + 0.5f * zt * (ho - hh);
            }
        }
        __syncwarp(gmask);
        #pragma unroll
        for (int i = 0; i < 5; i++) {
            ph2a[q * 5 + i] = h2oa[i];
            ph2b[q * 5 + i] = h2ob[i];
        }
        __syncwarp(gmask);
    }

    // -------- dense head --------
    {
        float hva[HID], hvb[HID];
        #pragma unroll
        for (int k = 0; k < HID; k++) { hva[k] = ph2a[k]; hvb[k] = ph2b[k]; }
        #pragma unroll
        for (int c = 0; c < 4; c++) {
            int col = q * 4 + c;
            if (col >= NLABEL) break;
            float da = sbd[col], db = sbd[col];
            #pragma unroll
            for (int k = 0; k < HID; k++) {
                float w = sWd[k * 16 + col];
                da = fmaf(hva[k], w, da);
                db = fmaf(hvb[k], w, db);
            }
            out[rowa * NLABEL + col] = da;
            out[(rowa + 1) * NLABEL + col] = db;
        }
    }
}

// ---------------- launch ----------------
extern "C" void kernel_launch(void* const* d_in, const int* in_sizes, int n_in,
                              void* d_out, int out_size) {
    const int*   x    = (const int*)  d_in[0];
    const float* emb  = (const float*)d_in[1];
    const float* W1   = (const float*)d_in[2];
    const float* U1   = (const float*)d_in[3];
    const float* b1   = (const float*)d_in[4];
    const float* W2   = (const float*)d_in[5];
    const float* U2   = (const float*)d_in[6];
    const float* b2   = (const float*)d_in[7];
    const float* Wd   = (const float*)d_in[8];
    const float* bd   = (const float*)d_in[9];
    float* out = (float*)d_out;

    prep_P_kernel<<<(VOCAB + VPB - 1) / VPB, 256>>>(emb, W1, b1);
    gru_main_kernel<<<(BATCH + RPB - 1) / RPB, BLOCK>>>(x, U1, b1, W2, U2, b2, Wd, bd, out);
}